// round 2
// baseline (speedup 1.0000x reference)
#include <cuda_runtime.h>
#include <math.h>

#define B_DIM 2
#define C_DIM 1024
#define T_DIM 2048
#define H_DIM 16
#define DH    64

// Scratch (allowed: __device__ globals, no runtime allocation)
__device__ float g_qkv[B_DIM * 3 * C_DIM * T_DIM];  // (B, 3C, T)  ~50 MB
__device__ float g_att[B_DIM * C_DIM * T_DIM];      // (B, C, T)   ~17 MB

// ---------------------------------------------------------------------------
// Generic batched SGEMM: C[b] = A (M x K, shared across batch) * B[b] (K x N)
// Row-major everywhere. Optional residual add.
// Tiles: 128x128x8, 256 threads, 8x8 per-thread microtile.
// Double-buffered smem: ONE __syncthreads per k-tile, global prefetch into
// registers overlapped with the FMA block.
// Requires M%128==0, N%128==0, K%8==0.
// ---------------------------------------------------------------------------
template <bool RES>
__global__ __launch_bounds__(256)
void sgemm128(const float* __restrict__ A, const float* __restrict__ Bg,
              float* __restrict__ Cg, const float* __restrict__ Rg,
              int M, int N, int K)
{
    const int bz = blockIdx.z;
    Bg += (long)bz * K * N;
    Cg += (long)bz * M * N;
    const float* Rb = RES ? (Rg + (long)bz * M * N) : nullptr;

    __shared__ float As[2][8][128];   // [buf][k][m] (transposed)
    __shared__ float Bs[2][8][128];   // [buf][k][n]

    const int tid = threadIdx.x;
    const int tx  = tid & 15;
    const int ty  = tid >> 4;
    const int m0  = blockIdx.y * 128;
    const int n0  = blockIdx.x * 128;

    const int arow = tid >> 1;          // 0..127
    const int acol = (tid & 1) * 4;     // 0 or 4
    const int brow = tid >> 5;          // 0..7
    const int bcol = (tid & 31) * 4;    // 0..124

    float acc[8][8];
    #pragma unroll
    for (int i = 0; i < 8; i++)
        #pragma unroll
        for (int j = 0; j < 8; j++) acc[i][j] = 0.0f;

    const float* Aptr = A  + (long)(m0 + arow) * K + acol;
    const float* Bptr = Bg + (long)brow * N + n0 + bcol;

    // Prologue: load k-tile 0 into buffer 0
    {
        float4 av = *(const float4*)(Aptr);
        As[0][acol + 0][arow] = av.x;
        As[0][acol + 1][arow] = av.y;
        As[0][acol + 2][arow] = av.z;
        As[0][acol + 3][arow] = av.w;
        *(float4*)&Bs[0][brow][bcol] = *(const float4*)(Bptr);
    }
    __syncthreads();

    int cur = 0;
    for (int k0 = 0; k0 < K; k0 += 8) {
        const bool has_next = (k0 + 8 < K);
        float4 av, bv;
        if (has_next) {
            av = *(const float4*)(Aptr + k0 + 8);
            bv = *(const float4*)(Bptr + (long)(k0 + 8) * N);
        }

        #pragma unroll
        for (int k = 0; k < 8; k++) {
            float a[8], b[8];
            *(float4*)&a[0] = *(const float4*)&As[cur][k][ty * 4];
            *(float4*)&a[4] = *(const float4*)&As[cur][k][64 + ty * 4];
            *(float4*)&b[0] = *(const float4*)&Bs[cur][k][tx * 4];
            *(float4*)&b[4] = *(const float4*)&Bs[cur][k][64 + tx * 4];
            #pragma unroll
            for (int i = 0; i < 8; i++)
                #pragma unroll
                for (int j = 0; j < 8; j++)
                    acc[i][j] += a[i] * b[j];
        }

        if (has_next) {
            const int nxt = cur ^ 1;
            As[nxt][acol + 0][arow] = av.x;
            As[nxt][acol + 1][arow] = av.y;
            As[nxt][acol + 2][arow] = av.z;
            As[nxt][acol + 3][arow] = av.w;
            *(float4*)&Bs[nxt][brow][bcol] = bv;
            cur = nxt;
            __syncthreads();
        }
    }

    #pragma unroll
    for (int i = 0; i < 8; i++) {
        int m = m0 + ((i < 4) ? (ty * 4 + i) : (64 + ty * 4 + (i - 4)));
        #pragma unroll
        for (int jg = 0; jg < 2; jg++) {
            int n = n0 + jg * 64 + tx * 4;
            float4 v;
            v.x = acc[i][jg * 4 + 0];
            v.y = acc[i][jg * 4 + 1];
            v.z = acc[i][jg * 4 + 2];
            v.w = acc[i][jg * 4 + 3];
            if (RES) {
                float4 r = *(const float4*)(Rb + (long)m * N + n);
                v.x += r.x; v.y += r.y; v.z += r.z; v.w += r.w;
            }
            *(float4*)(Cg + (long)m * N + n) = v;
        }
    }
}

// ---------------------------------------------------------------------------
// Fused flash attention for (dh=64) heads stored as (B, 3C, T) slices of qkv.
// Q[d,q] = qkv[b, h*64+d,       q]
// K[d,k] = qkv[b, C + h*64+d,   k]
// V[d,k] = qkv[b, 2C + h*64+d,  k]
// S = Q^T K (no 1/sqrt(dh) scaling -- faithful to reference), softmax over k,
// O[d,q] = sum_k P[q,k] V[d,k] -> out[b, h*64+d, q]
// Block: 64-q tile, loop 64-k tiles. 256 threads, 4x4 microtiles.
// ---------------------------------------------------------------------------
#define FL_SMEM ((4096 + 4096 + 64 * 68 + 64 * 68) * 4)

__global__ __launch_bounds__(256)
void flash64(const float* __restrict__ qkv, float* __restrict__ out)
{
    extern __shared__ float sm[];
    float* Qs = sm;                   // [64][64]  [d][q]
    float* Ks = sm + 4096;            // [64][64]  [d][k]
    float* Vs = sm + 8192;            // [64][68]  [k][d] (transposed, padded)
    float* Ps = sm + 8192 + 64 * 68;  // [64][68]  [k][q] (transposed, padded)

    const int tid = threadIdx.x;
    const int tx  = tid & 15;
    const int ty  = tid >> 4;
    const int q0  = blockIdx.x * 64;
    const int h   = blockIdx.y;
    const int b   = blockIdx.z;

    const long baseQ = ((long)b * 3 * C_DIM + h * DH) * T_DIM;
    const long baseK = baseQ + (long)C_DIM * T_DIM;
    const long baseV = baseQ + 2L * C_DIM * T_DIM;

    const int lrow = tid >> 4;        // 0..15 (+16*i)
    const int lcol = (tid & 15) * 4;  // 0..60

    // Load Q tile once
    #pragma unroll
    for (int i = 0; i < 4; i++) {
        int d = lrow + 16 * i;
        *(float4*)&Qs[d * 64 + lcol] =
            *(const float4*)(qkv + baseQ + (long)d * T_DIM + q0 + lcol);
    }

    float m[4], l[4], o[4][4];
    #pragma unroll
    for (int i = 0; i < 4; i++) {
        m[i] = -INFINITY;
        l[i] = 0.0f;
        #pragma unroll
        for (int j = 0; j < 4; j++) o[i][j] = 0.0f;
    }

    for (int kt = 0; kt < T_DIM / 64; kt++) {
        const int k0 = kt * 64;
        __syncthreads();   // previous PV gemm done before overwriting Ks/Vs
        #pragma unroll
        for (int i = 0; i < 4; i++) {
            int d = lrow + 16 * i;
            *(float4*)&Ks[d * 64 + lcol] =
                *(const float4*)(qkv + baseK + (long)d * T_DIM + k0 + lcol);
            float4 vv = *(const float4*)(qkv + baseV + (long)d * T_DIM + k0 + lcol);
            Vs[(lcol + 0) * 68 + d] = vv.x;
            Vs[(lcol + 1) * 68 + d] = vv.y;
            Vs[(lcol + 2) * 68 + d] = vv.z;
            Vs[(lcol + 3) * 68 + d] = vv.w;
        }
        __syncthreads();

        // S tile: s[i][j] = S[q0+ty*4+i][k0+tx*4+j]
        float s[4][4];
        #pragma unroll
        for (int i = 0; i < 4; i++)
            #pragma unroll
            for (int j = 0; j < 4; j++) s[i][j] = 0.0f;

        #pragma unroll 8
        for (int d = 0; d < 64; d++) {
            float aq[4], ak[4];
            *(float4*)aq = *(const float4*)&Qs[d * 64 + ty * 4];
            *(float4*)ak = *(const float4*)&Ks[d * 64 + tx * 4];
            #pragma unroll
            for (int i = 0; i < 4; i++)
                #pragma unroll
                for (int j = 0; j < 4; j++)
                    s[i][j] += aq[i] * ak[j];
        }

        // Online softmax per q-row (reduce across the 16 tx lanes of a half-warp)
        #pragma unroll
        for (int i = 0; i < 4; i++) {
            float rm = fmaxf(fmaxf(s[i][0], s[i][1]), fmaxf(s[i][2], s[i][3]));
            #pragma unroll
            for (int off = 8; off >= 1; off >>= 1)
                rm = fmaxf(rm, __shfl_xor_sync(0xffffffffu, rm, off));
            float mnew = fmaxf(m[i], rm);
            float sc = __expf(m[i] - mnew);
            m[i] = mnew;
            float rs = 0.0f;
            #pragma unroll
            for (int j = 0; j < 4; j++) {
                float p = __expf(s[i][j] - mnew);
                s[i][j] = p;
                rs += p;
            }
            #pragma unroll
            for (int off = 8; off >= 1; off >>= 1)
                rs += __shfl_xor_sync(0xffffffffu, rs, off);
            l[i] = l[i] * sc + rs;
            #pragma unroll
            for (int j = 0; j < 4; j++) o[i][j] *= sc;
            // Stage P transposed: Ps[k][q]
            #pragma unroll
            for (int j = 0; j < 4; j++)
                Ps[(tx * 4 + j) * 68 + ty * 4 + i] = s[i][j];
        }
        __syncthreads();

        // O accumulate: o[i][j] += sum_k P[q][k] * V[d][k]
        //   q = ty*4+i (from Ps[k][q]), d = tx*4+j (from Vs[k][d])
        #pragma unroll 8
        for (int k = 0; k < 64; k++) {
            float fp[4], fv[4];
            *(float4*)fp = *(const float4*)&Ps[k * 68 + ty * 4];
            *(float4*)fv = *(const float4*)&Vs[k * 68 + tx * 4];
            #pragma unroll
            for (int i = 0; i < 4; i++)
                #pragma unroll
                for (int j = 0; j < 4; j++)
                    o[i][j] += fp[i] * fv[j];
        }
    }

    // Normalize and stage output into Qs as [d][q] for coalesced writeout
    __syncthreads();
    #pragma unroll
    for (int i = 0; i < 4; i++) {
        float inv = 1.0f / l[i];
        #pragma unroll
        for (int j = 0; j < 4; j++)
            Qs[(tx * 4 + j) * 64 + ty * 4 + i] = o[i][j] * inv;
    }
    __syncthreads();

    const long baseO = ((long)b * C_DIM + h * DH) * T_DIM;
    #pragma unroll
    for (int i = 0; i < 4; i++) {
        int d = lrow + 16 * i;
        *(float4*)(out + baseO + (long)d * T_DIM + q0 + lcol) =
            *(const float4*)&Qs[d * 64 + lcol];
    }
}

// ---------------------------------------------------------------------------
// LayerNorm over channel dim per (b, t), in-place on (B, C, T) buffer.
// Block: 256 threads = 64 t-positions x 4-way C split.
// ---------------------------------------------------------------------------
__global__ __launch_bounds__(256)
void layernorm_k(float* __restrict__ out, const float* __restrict__ gamma,
                 const float* __restrict__ beta)
{
    const int tid = threadIdx.x;
    const int tt  = tid & 63;
    const int cc  = tid >> 6;   // 0..3
    const int t   = blockIdx.x * 64 + tt;
    const int b   = blockIdx.y;
    float* base = out + (long)b * C_DIM * T_DIM + t;

    float s = 0.0f, ss = 0.0f;
    #pragma unroll 8
    for (int c = cc; c < C_DIM; c += 4) {
        float v = base[(long)c * T_DIM];
        s += v;
        ss += v * v;
    }
    __shared__ float sS[4][64], sQ[4][64];
    sS[cc][tt] = s;
    sQ[cc][tt] = ss;
    __syncthreads();
    float tot  = sS[0][tt] + sS[1][tt] + sS[2][tt] + sS[3][tt];
    float totq = sQ[0][tt] + sQ[1][tt] + sQ[2][tt] + sQ[3][tt];
    float mu   = tot * (1.0f / C_DIM);
    float var  = totq * (1.0f / C_DIM) - mu * mu;
    float rinv = rsqrtf(var + 1e-6f);

    #pragma unroll 8
    for (int c = cc; c < C_DIM; c += 4) {
        float v = base[(long)c * T_DIM];
        base[(long)c * T_DIM] = (v - mu) * rinv * gamma[c] + beta[c];
    }
}

// ---------------------------------------------------------------------------
extern "C" void kernel_launch(void* const* d_in, const int* in_sizes, int n_in,
                              void* d_out, int out_size)
{
    const float* x     = (const float*)d_in[0];  // (B, C, T)
    const float* w_qkv = (const float*)d_in[1];  // (3C, C)
    const float* w_fc  = (const float*)d_in[2];  // (C, C)
    const float* gamma = (const float*)d_in[3];  // (C,)
    const float* beta  = (const float*)d_in[4];  // (C,)
    float* out = (float*)d_out;                  // (B, C, T)

    float *qkv, *att;
    cudaGetSymbolAddress((void**)&qkv, g_qkv);
    cudaGetSymbolAddress((void**)&att, g_att);

    // 1) QKV projection: (3C x C) @ (B, C, T) -> (B, 3C, T)
    sgemm128<false><<<dim3(T_DIM / 128, 3 * C_DIM / 128, B_DIM), 256>>>(
        w_qkv, x, qkv, nullptr, 3 * C_DIM, T_DIM, C_DIM);

    // 2) Fused flash attention -> (B, C, T)
    cudaFuncSetAttribute(flash64, cudaFuncAttributeMaxDynamicSharedMemorySize,
                         FL_SMEM);
    flash64<<<dim3(T_DIM / 64, H_DIM, B_DIM), 256, FL_SMEM>>>(qkv, att);

    // 3) FC projection + residual: (C x C) @ (B, C, T) + x -> out
    sgemm128<true><<<dim3(T_DIM / 128, C_DIM / 128, B_DIM), 256>>>(
        w_fc, att, out, x, C_DIM, T_DIM, C_DIM);

    // 4) LayerNorm over channels, in-place on out
    layernorm_k<<<dim3(T_DIM / 64, B_DIM), 256>>>(out, gamma, beta);
}

// round 4
// speedup vs baseline: 1.2864x; 1.2864x over previous
#include <cuda_runtime.h>
#include <cuda_bf16.h>
#include <math.h>
#include <stdint.h>

#define B_DIM 2
#define C_DIM 1024
#define T_DIM 2048
#define H_DIM 16
#define DH    64
#define KTOT  1024

// ---------------------------------------------------------------------------
// Scratch (__device__ globals; no runtime allocation)
// ---------------------------------------------------------------------------
__device__ float g_qkv[B_DIM * 3 * C_DIM * T_DIM];            // (B, 3C, T) fp32
__device__ float g_att[B_DIM * C_DIM * T_DIM];                // (B, C, T)  fp32
__device__ __nv_bfloat16 g_wqkv_hi[3 * C_DIM * C_DIM];        // [3C, C]
__device__ __nv_bfloat16 g_wqkv_lo[3 * C_DIM * C_DIM];
__device__ __nv_bfloat16 g_wfc_hi[C_DIM * C_DIM];             // [C, C]
__device__ __nv_bfloat16 g_wfc_lo[C_DIM * C_DIM];
__device__ __nv_bfloat16 g_xT_hi[B_DIM * T_DIM * C_DIM];      // (B, T, C)
__device__ __nv_bfloat16 g_xT_lo[B_DIM * T_DIM * C_DIM];
__device__ __nv_bfloat16 g_attT_hi[B_DIM * T_DIM * C_DIM];    // (B, T, C)
__device__ __nv_bfloat16 g_attT_lo[B_DIM * T_DIM * C_DIM];

// ---------------------------------------------------------------------------
// Helpers (baseline PTX only: sm_80+ features, compile for plain sm_100)
// ---------------------------------------------------------------------------
__device__ __forceinline__ uint32_t smem_u32(const void* p) {
    uint32_t a;
    asm("{ .reg .u64 t; cvta.to.shared.u64 t, %1; cvt.u32.u64 %0, t; }"
        : "=r"(a) : "l"(p));
    return a;
}
__device__ __forceinline__ uint32_t lds32(uint32_t addr) {
    uint32_t v;
    asm volatile("ld.shared.b32 %0, [%1];" : "=r"(v) : "r"(addr));
    return v;
}
__device__ __forceinline__ void cp16(uint32_t s, const void* g) {
    asm volatile("cp.async.cg.shared.global [%0], [%1], 16;"
                 :: "r"(s), "l"(g));
}
#define CP_COMMIT() asm volatile("cp.async.commit_group;" ::: "memory")
#define CP_WAIT(N)  asm volatile("cp.async.wait_group %0;" :: "n"(N) : "memory")

__device__ __forceinline__ void mma_bf16(float* c, const uint32_t* a,
                                         const uint32_t* b) {
    asm volatile(
        "mma.sync.aligned.m16n8k16.row.col.f32.bf16.bf16.f32 "
        "{%0,%1,%2,%3}, {%4,%5,%6,%7}, {%8,%9}, {%0,%1,%2,%3};"
        : "+f"(c[0]), "+f"(c[1]), "+f"(c[2]), "+f"(c[3])
        : "r"(a[0]), "r"(a[1]), "r"(a[2]), "r"(a[3]), "r"(b[0]), "r"(b[1]));
}

// ---------------------------------------------------------------------------
// Split/transpose conversion kernels
// ---------------------------------------------------------------------------
__global__ __launch_bounds__(256)
void conv_split(const float* __restrict__ src, __nv_bfloat16* __restrict__ hi,
                __nv_bfloat16* __restrict__ lo, int n4)
{
    int i = blockIdx.x * 256 + threadIdx.x;
    if (i >= n4) return;
    float4 v = ((const float4*)src)[i];
    float f[4] = {v.x, v.y, v.z, v.w};
    __nv_bfloat162 ph, pl;
    __nv_bfloat16 h0 = __float2bfloat16(f[0]);
    __nv_bfloat16 h1 = __float2bfloat16(f[1]);
    __nv_bfloat16 h2 = __float2bfloat16(f[2]);
    __nv_bfloat16 h3 = __float2bfloat16(f[3]);
    ph.x = h0; ph.y = h1; ((__nv_bfloat162*)hi)[i * 2 + 0] = ph;
    ph.x = h2; ph.y = h3; ((__nv_bfloat162*)hi)[i * 2 + 1] = ph;
    pl.x = __float2bfloat16(f[0] - __bfloat162float(h0));
    pl.y = __float2bfloat16(f[1] - __bfloat162float(h1));
    ((__nv_bfloat162*)lo)[i * 2 + 0] = pl;
    pl.x = __float2bfloat16(f[2] - __bfloat162float(h2));
    pl.y = __float2bfloat16(f[3] - __bfloat162float(h3));
    ((__nv_bfloat162*)lo)[i * 2 + 1] = pl;
}

// (B, C, T) fp32 -> (B, T, C) bf16 hi/lo
__global__ __launch_bounds__(256)
void conv_T_split(const float* __restrict__ src, __nv_bfloat16* __restrict__ hi,
                  __nv_bfloat16* __restrict__ lo)
{
    __shared__ float tile[32][33];
    const int tx = threadIdx.x & 31, ty = threadIdx.x >> 5;  // ty 0..7
    const int t0 = blockIdx.x * 32, c0 = blockIdx.y * 32, b = blockIdx.z;
    const float* s = src + (long)b * C_DIM * T_DIM;
    #pragma unroll
    for (int r = 0; r < 4; r++)
        tile[ty + 8 * r][tx] = s[(long)(c0 + ty + 8 * r) * T_DIM + t0 + tx];
    __syncthreads();
    const long ob = (long)b * T_DIM * C_DIM;
    #pragma unroll
    for (int r = 0; r < 4; r++) {
        float v = tile[tx][ty + 8 * r];
        __nv_bfloat16 h = __float2bfloat16(v);
        long o = ob + (long)(t0 + ty + 8 * r) * C_DIM + c0 + tx;
        hi[o] = h;
        lo[o] = __float2bfloat16(v - __bfloat162float(h));
    }
}

// ---------------------------------------------------------------------------
// mma.sync bf16x3 GEMM: C[b][m][n] = sum_k A[m][k] * BT[b][n][k]  (+residual)
// A [M,K] bf16 hi/lo (weights); BT (B, T, K) bf16 hi/lo; C (B, M, T) fp32.
// CTA: 128m x 128n, 8 warps (4m x 2n), each warp 32m x 64n.
// K chunked by 32, double-buffered smem via cp.async.
// ---------------------------------------------------------------------------
#define KC      32
#define NCHUNK  (KTOT / KC)        // 32
#define STRIDE  40                 // smem row stride in elements (80B, 16B-aligned)
#define SPLIT_B (128 * STRIDE * 2) // 10240 bytes per split tile
#define BUF_B   (4 * SPLIT_B)      // 40960 bytes per buffer (AH, AL, BH, BL)
#define GSMEM   (2 * BUF_B)        // 81920 bytes

__device__ __forceinline__ void issue_chunk(
    uint32_t sbuf, const __nv_bfloat16* ah, const __nv_bfloat16* al,
    const __nv_bfloat16* bh, const __nv_bfloat16* bl, int k0, int tid)
{
    const __nv_bfloat16* srcs[4] = {ah, al, bh, bl};
    #pragma unroll
    for (int s4 = 0; s4 < 4; s4++) {
        #pragma unroll
        for (int t = 0; t < 2; t++) {
            int idx = tid + t * 256;         // 0..511
            int row = idx >> 2;              // 0..127
            int c16 = idx & 3;               // 0..3 (8 elems each)
            cp16(sbuf + s4 * SPLIT_B + (row * STRIDE + c16 * 8) * 2,
                 srcs[s4] + (long)row * KTOT + k0 + c16 * 8);
        }
    }
}

template <bool RES>
__global__ __launch_bounds__(256)
void mma_gemm(const __nv_bfloat16* __restrict__ Ahi,
              const __nv_bfloat16* __restrict__ Alo,
              const __nv_bfloat16* __restrict__ BThi,
              const __nv_bfloat16* __restrict__ BTlo,
              float* __restrict__ Cg, const float* __restrict__ Rg, int M)
{
    extern __shared__ char smem[];
    const uint32_t sb = smem_u32(smem);
    const int tid  = threadIdx.x;
    const int lane = tid & 31;
    const int wid  = tid >> 5;
    const int wm   = wid & 3;          // warp m index (0..3)
    const int wn   = wid >> 2;         // warp n index (0..1)
    const int lr   = lane >> 2;        // 0..7
    const int lc   = (lane & 3) * 2;   // 0,2,4,6

    const int m0 = blockIdx.y * 128;
    const int n0 = blockIdx.x * 128;
    const int b  = blockIdx.z;

    const __nv_bfloat16* Ah = Ahi + (long)m0 * KTOT;
    const __nv_bfloat16* Al = Alo + (long)m0 * KTOT;
    const __nv_bfloat16* Bh = BThi + (long)b * T_DIM * KTOT + (long)n0 * KTOT;
    const __nv_bfloat16* Bl = BTlo + (long)b * T_DIM * KTOT + (long)n0 * KTOT;
    float* Cb = Cg + (long)b * M * T_DIM;
    const float* Rb = RES ? (Rg + (long)b * M * T_DIM) : nullptr;

    float acc[2][8][4];
    #pragma unroll
    for (int mt = 0; mt < 2; mt++)
        #pragma unroll
        for (int nt = 0; nt < 8; nt++)
            #pragma unroll
            for (int r = 0; r < 4; r++) acc[mt][nt][r] = 0.0f;

    // Prologue: chunk 0 into buffer 0
    issue_chunk(sb, Ah, Al, Bh, Bl, 0, tid);
    CP_COMMIT();

    for (int i = 0; i < NCHUNK; i++) {
        const int buf = i & 1;
        if (i + 1 < NCHUNK) {
            issue_chunk(sb + ((i + 1) & 1) * BUF_B, Ah, Al, Bh, Bl,
                        (i + 1) * KC, tid);
            CP_COMMIT();
            CP_WAIT(1);
        } else {
            CP_WAIT(0);
        }
        __syncthreads();

        const uint32_t sbuf = sb + buf * BUF_B;
        #pragma unroll
        for (int kh = 0; kh < 2; kh++) {
            uint32_t ah[2][4], al[2][4];
            #pragma unroll
            for (int mt = 0; mt < 2; mt++) {
                uint32_t base = sbuf +
                    ((wm * 32 + mt * 16 + lr) * STRIDE + kh * 16 + lc) * 2;
                ah[mt][0] = lds32(base);
                ah[mt][1] = lds32(base + 8 * STRIDE * 2);
                ah[mt][2] = lds32(base + 16);
                ah[mt][3] = lds32(base + 8 * STRIDE * 2 + 16);
                al[mt][0] = lds32(base + SPLIT_B);
                al[mt][1] = lds32(base + SPLIT_B + 8 * STRIDE * 2);
                al[mt][2] = lds32(base + SPLIT_B + 16);
                al[mt][3] = lds32(base + SPLIT_B + 8 * STRIDE * 2 + 16);
            }
            uint32_t bhf[8][2], blf[8][2];
            #pragma unroll
            for (int nt = 0; nt < 8; nt++) {
                uint32_t base = sbuf + 2 * SPLIT_B +
                    ((wn * 64 + nt * 8 + lr) * STRIDE + kh * 16 + lc) * 2;
                bhf[nt][0] = lds32(base);
                bhf[nt][1] = lds32(base + 16);
                blf[nt][0] = lds32(base + SPLIT_B);
                blf[nt][1] = lds32(base + SPLIT_B + 16);
            }
            #pragma unroll
            for (int mt = 0; mt < 2; mt++)
                #pragma unroll
                for (int nt = 0; nt < 8; nt++) {
                    mma_bf16(acc[mt][nt], ah[mt], bhf[nt]);
                    mma_bf16(acc[mt][nt], ah[mt], blf[nt]);
                    mma_bf16(acc[mt][nt], al[mt], bhf[nt]);
                }
        }
        __syncthreads();
    }

    // Epilogue: C frags -> global (+residual)
    const int mb = m0 + wm * 32;
    const int nb = n0 + wn * 64;
    #pragma unroll
    for (int mt = 0; mt < 2; mt++) {
        #pragma unroll
        for (int nt = 0; nt < 8; nt++) {
            int r = mb + mt * 16 + lr;
            int c = nb + nt * 8 + lc;
            long o0 = (long)r * T_DIM + c;
            long o1 = o0 + 8L * T_DIM;
            float2 v0 = make_float2(acc[mt][nt][0], acc[mt][nt][1]);
            float2 v1 = make_float2(acc[mt][nt][2], acc[mt][nt][3]);
            if (RES) {
                float2 r0 = *(const float2*)(Rb + o0);
                float2 r1 = *(const float2*)(Rb + o1);
                v0.x += r0.x; v0.y += r0.y;
                v1.x += r1.x; v1.y += r1.y;
            }
            *(float2*)(Cb + o0) = v0;
            *(float2*)(Cb + o1) = v1;
        }
    }
}

// ---------------------------------------------------------------------------
// Fused flash attention (fp32 SIMT), unchanged (known-correct).
// ---------------------------------------------------------------------------
#define FL_SMEM ((4096 + 4096 + 64 * 68 + 64 * 68) * 4)

__global__ __launch_bounds__(256)
void flash64(const float* __restrict__ qkv, float* __restrict__ out)
{
    extern __shared__ float sm[];
    float* Qs = sm;
    float* Ks = sm + 4096;
    float* Vs = sm + 8192;
    float* Ps = sm + 8192 + 64 * 68;

    const int tid = threadIdx.x;
    const int tx  = tid & 15;
    const int ty  = tid >> 4;
    const int q0  = blockIdx.x * 64;
    const int h   = blockIdx.y;
    const int b   = blockIdx.z;

    const long baseQ = ((long)b * 3 * C_DIM + h * DH) * T_DIM;
    const long baseK = baseQ + (long)C_DIM * T_DIM;
    const long baseV = baseQ + 2L * C_DIM * T_DIM;

    const int lrow = tid >> 4;
    const int lcol = (tid & 15) * 4;

    #pragma unroll
    for (int i = 0; i < 4; i++) {
        int d = lrow + 16 * i;
        *(float4*)&Qs[d * 64 + lcol] =
            *(const float4*)(qkv + baseQ + (long)d * T_DIM + q0 + lcol);
    }

    float m[4], l[4], o[4][4];
    #pragma unroll
    for (int i = 0; i < 4; i++) {
        m[i] = -INFINITY;
        l[i] = 0.0f;
        #pragma unroll
        for (int j = 0; j < 4; j++) o[i][j] = 0.0f;
    }

    for (int kt = 0; kt < T_DIM / 64; kt++) {
        const int k0 = kt * 64;
        __syncthreads();
        #pragma unroll
        for (int i = 0; i < 4; i++) {
            int d = lrow + 16 * i;
            *(float4*)&Ks[d * 64 + lcol] =
                *(const float4*)(qkv + baseK + (long)d * T_DIM + k0 + lcol);
            float4 vv = *(const float4*)(qkv + baseV + (long)d * T_DIM + k0 + lcol);
            Vs[(lcol + 0) * 68 + d] = vv.x;
            Vs[(lcol + 1) * 68 + d] = vv.y;
            Vs[(lcol + 2) * 68 + d] = vv.z;
            Vs[(lcol + 3) * 68 + d] = vv.w;
        }
        __syncthreads();

        float s[4][4];
        #pragma unroll
        for (int i = 0; i < 4; i++)
            #pragma unroll
            for (int j = 0; j < 4; j++) s[i][j] = 0.0f;

        #pragma unroll 8
        for (int d = 0; d < 64; d++) {
            float aq[4], ak[4];
            *(float4*)aq = *(const float4*)&Qs[d * 64 + ty * 4];
            *(float4*)ak = *(const float4*)&Ks[d * 64 + tx * 4];
            #pragma unroll
            for (int i = 0; i < 4; i++)
                #pragma unroll
                for (int j = 0; j < 4; j++)
                    s[i][j] += aq[i] * ak[j];
        }

        #pragma unroll
        for (int i = 0; i < 4; i++) {
            float rm = fmaxf(fmaxf(s[i][0], s[i][1]), fmaxf(s[i][2], s[i][3]));
            #pragma unroll
            for (int off = 8; off >= 1; off >>= 1)
                rm = fmaxf(rm, __shfl_xor_sync(0xffffffffu, rm, off));
            float mnew = fmaxf(m[i], rm);
            float sc = __expf(m[i] - mnew);
            m[i] = mnew;
            float rs = 0.0f;
            #pragma unroll
            for (int j = 0; j < 4; j++) {
                float p = __expf(s[i][j] - mnew);
                s[i][j] = p;
                rs += p;
            }
            #pragma unroll
            for (int off = 8; off >= 1; off >>= 1)
                rs += __shfl_xor_sync(0xffffffffu, rs, off);
            l[i] = l[i] * sc + rs;
            #pragma unroll
            for (int j = 0; j < 4; j++) o[i][j] *= sc;
            #pragma unroll
            for (int j = 0; j < 4; j++)
                Ps[(tx * 4 + j) * 68 + ty * 4 + i] = s[i][j];
        }
        __syncthreads();

        #pragma unroll 8
        for (int k = 0; k < 64; k++) {
            float fp[4], fv[4];
            *(float4*)fp = *(const float4*)&Ps[k * 68 + ty * 4];
            *(float4*)fv = *(const float4*)&Vs[k * 68 + tx * 4];
            #pragma unroll
            for (int i = 0; i < 4; i++)
                #pragma unroll
                for (int j = 0; j < 4; j++)
                    o[i][j] += fp[i] * fv[j];
        }
    }

    __syncthreads();
    #pragma unroll
    for (int i = 0; i < 4; i++) {
        float inv = 1.0f / l[i];
        #pragma unroll
        for (int j = 0; j < 4; j++)
            Qs[(tx * 4 + j) * 64 + ty * 4 + i] = o[i][j] * inv;
    }
    __syncthreads();

    const long baseO = ((long)b * C_DIM + h * DH) * T_DIM;
    #pragma unroll
    for (int i = 0; i < 4; i++) {
        int d = lrow + 16 * i;
        *(float4*)(out + baseO + (long)d * T_DIM + q0 + lcol) =
            *(const float4*)&Qs[d * 64 + lcol];
    }
}

// ---------------------------------------------------------------------------
// LayerNorm (unchanged)
// ---------------------------------------------------------------------------
__global__ __launch_bounds__(256)
void layernorm_k(float* __restrict__ out, const float* __restrict__ gamma,
                 const float* __restrict__ beta)
{
    const int tid = threadIdx.x;
    const int tt  = tid & 63;
    const int cc  = tid >> 6;
    const int t   = blockIdx.x * 64 + tt;
    const int b   = blockIdx.y;
    float* base = out + (long)b * C_DIM * T_DIM + t;

    float s = 0.0f, ss = 0.0f;
    #pragma unroll 8
    for (int c = cc; c < C_DIM; c += 4) {
        float v = base[(long)c * T_DIM];
        s += v;
        ss += v * v;
    }
    __shared__ float sS[4][64], sQ[4][64];
    sS[cc][tt] = s;
    sQ[cc][tt] = ss;
    __syncthreads();
    float tot  = sS[0][tt] + sS[1][tt] + sS[2][tt] + sS[3][tt];
    float totq = sQ[0][tt] + sQ[1][tt] + sQ[2][tt] + sQ[3][tt];
    float mu   = tot * (1.0f / C_DIM);
    float var  = totq * (1.0f / C_DIM) - mu * mu;
    float rinv = rsqrtf(var + 1e-6f);

    #pragma unroll 8
    for (int c = cc; c < C_DIM; c += 4) {
        float v = base[(long)c * T_DIM];
        base[(long)c * T_DIM] = (v - mu) * rinv * gamma[c] + beta[c];
    }
}

// ---------------------------------------------------------------------------
extern "C" void kernel_launch(void* const* d_in, const int* in_sizes, int n_in,
                              void* d_out, int out_size)
{
    const float* x     = (const float*)d_in[0];
    const float* w_qkv = (const float*)d_in[1];
    const float* w_fc  = (const float*)d_in[2];
    const float* gamma = (const float*)d_in[3];
    const float* beta  = (const float*)d_in[4];
    float* out = (float*)d_out;

    float *qkv, *att;
    cudaGetSymbolAddress((void**)&qkv, g_qkv);
    cudaGetSymbolAddress((void**)&att, g_att);
    __nv_bfloat16 *wqh, *wql, *wfh, *wfl, *xth, *xtl, *ath, *atl;
    cudaGetSymbolAddress((void**)&wqh, g_wqkv_hi);
    cudaGetSymbolAddress((void**)&wql, g_wqkv_lo);
    cudaGetSymbolAddress((void**)&wfh, g_wfc_hi);
    cudaGetSymbolAddress((void**)&wfl, g_wfc_lo);
    cudaGetSymbolAddress((void**)&xth, g_xT_hi);
    cudaGetSymbolAddress((void**)&xtl, g_xT_lo);
    cudaGetSymbolAddress((void**)&ath, g_attT_hi);
    cudaGetSymbolAddress((void**)&atl, g_attT_lo);

    cudaFuncSetAttribute(mma_gemm<false>,
                         cudaFuncAttributeMaxDynamicSharedMemorySize, GSMEM);
    cudaFuncSetAttribute(mma_gemm<true>,
                         cudaFuncAttributeMaxDynamicSharedMemorySize, GSMEM);
    cudaFuncSetAttribute(flash64,
                         cudaFuncAttributeMaxDynamicSharedMemorySize, FL_SMEM);

    // Split weights into bf16 hi/lo
    conv_split<<<(3 * C_DIM * C_DIM / 4 + 255) / 256, 256>>>(
        w_qkv, wqh, wql, 3 * C_DIM * C_DIM / 4);
    conv_split<<<(C_DIM * C_DIM / 4 + 255) / 256, 256>>>(
        w_fc, wfh, wfl, C_DIM * C_DIM / 4);
    // Transpose + split x: (B,C,T) -> (B,T,C)
    conv_T_split<<<dim3(T_DIM / 32, C_DIM / 32, B_DIM), 256>>>(x, xth, xtl);

    // 1) QKV projection (mma.sync bf16x3): (3C x C) @ X -> (B, 3C, T)
    mma_gemm<false><<<dim3(T_DIM / 128, 3 * C_DIM / 128, B_DIM), 256, GSMEM>>>(
        wqh, wql, xth, xtl, qkv, nullptr, 3 * C_DIM);

    // 2) Flash attention -> (B, C, T)
    flash64<<<dim3(T_DIM / 64, H_DIM, B_DIM), 256, FL_SMEM>>>(qkv, att);

    // Transpose + split attention output
    conv_T_split<<<dim3(T_DIM / 32, C_DIM / 32, B_DIM), 256>>>(att, ath, atl);

    // 3) FC projection + residual (mma.sync bf16x3)
    mma_gemm<true><<<dim3(T_DIM / 128, C_DIM / 128, B_DIM), 256, GSMEM>>>(
        wfh, wfl, ath, atl, out, x, C_DIM);

    // 4) LayerNorm
    layernorm_k<<<dim3(T_DIM / 64, B_DIM), 256>>>(out, gamma, beta);
}